// round 16
// baseline (speedup 1.0000x reference)
#include <cuda_runtime.h>
#include <cuda_bf16.h>
#include <cstdint>
#include <math.h>

// ---------------- problem constants ----------------
#define T_STEPS 1024
#define B_SZ    64
#define H_SZ    2048
#define G3H     6144

// ---------------- kernel config ----------------
#define NCTA   128          // persistent CTAs; CTA m owns gate units [16m,16m+16)
#define NTH    256          // 8 warps; each warp: 3 mt (r/z/n rows) x 8 nt, k-split 8-way
#define MT_TOT 384          // total m16 tiles
#define KT_N   128          // k16 tiles (2048/16)
#define KT_PW  16           // kt iterations per warp (KT_N/8)
#define KS_N   8            // k-split ways
#define COLP   66           // padded smem D row stride (floats)

// persistent smem layout (floats)
#define SM_DP   0                           // [ks8][gate3][row16][COLP] = 25344
#define SM_HF   (KS_N*3*16*COLP)            // fp32 h_old [16][64]
#define SM_GC   (SM_HF + 1024)              // gate coefs [16 units][3 gates][4]
#define SM_BN   (SM_GC + 192)               // bias_n [16]
#define SMEM_DYN ((SM_BN + 16) * 4)

// ---------------- persistent device state (fragment-ordered images) ----------------
// W: [phase(hi/lo)][mt 384][kt 128][lane 32] x 16B  (+1-kt pad)
__device__ uint4 g_w[(size_t)2 * MT_TOT * KT_N * 32 + 32];
// h: [parity 2][nt 8][kt 128][lane 32] x 16B = (hi.b01, hi.b89, lo.b01, lo.b89)  (+1-kt pad)
#define HBUF ((size_t)8 * KT_N * 32)
__device__ uint4 g_h[2 * HBUF + 32];
// two-level barrier state
__device__ unsigned g_leaf[16 * 32];        // 16 leaf counters, 128B apart
__device__ unsigned g_root = 0;
__device__ unsigned g_release = 0;

// ---------------- helpers ----------------
__device__ __forceinline__ unsigned pk_bf16(float x, float y, int ph) {
    __nv_bfloat16 hx = __float2bfloat16_rn(x);
    __nv_bfloat16 hy = __float2bfloat16_rn(y);
    if (ph) {
        hx = __float2bfloat16_rn(x - __bfloat162float(hx));
        hy = __float2bfloat16_rn(y - __bfloat162float(hy));
    }
    return ((unsigned)*(unsigned short*)&hy << 16) | *(unsigned short*)&hx;
}

#define MMAOP(d, A, bx, by) \
    asm volatile("mma.sync.aligned.m16n8k16.row.col.f32.bf16.bf16.f32 " \
                 "{%0,%1,%2,%3}, {%4,%5,%6,%7}, {%8,%9}, {%0,%1,%2,%3};" \
                 : "+f"((d)[0]), "+f"((d)[1]), "+f"((d)[2]), "+f"((d)[3]) \
                 : "r"((A).x), "r"((A).y), "r"((A).z), "r"((A).w), \
                   "r"(bx), "r"(by))

// ---------------- init kernels (fragment images) ----------------
__global__ void w_init(const float* __restrict__ whh) {
    int id = blockIdx.x * 256 + threadIdx.x;   // 2*384*128*32 = 3,145,728
    int lane = id & 31;  id >>= 5;
    int kt   = id & 127; id >>= 7;
    int mt   = id % MT_TOT;
    int ph   = id / MT_TOT;
    int r0 = mt * 16 + (lane >> 2);
    int k0 = kt * 16 + (lane & 3) * 2;
    float2 a0 = *(const float2*)&whh[(size_t)r0 * H_SZ + k0];
    float2 a1 = *(const float2*)&whh[(size_t)(r0 + 8) * H_SZ + k0];
    float2 a2 = *(const float2*)&whh[(size_t)r0 * H_SZ + k0 + 8];
    float2 a3 = *(const float2*)&whh[(size_t)(r0 + 8) * H_SZ + k0 + 8];
    uint4 v;
    v.x = pk_bf16(a0.x, a0.y, ph);
    v.y = pk_bf16(a1.x, a1.y, ph);
    v.z = pk_bf16(a2.x, a2.y, ph);
    v.w = pk_bf16(a3.x, a3.y, ph);
    g_w[(((size_t)ph * MT_TOT + mt) * KT_N + kt) * 32 + lane] = v;
}

__global__ void h_init(const float* __restrict__ h0) {
    int id = blockIdx.x * 256 + threadIdx.x;   // 32768 (parity-0 buffer)
    int lane = id & 31;  id >>= 5;
    int kt   = id & 127; id >>= 7;
    int nt   = id & 7;
    int b  = nt * 8 + (lane >> 2);
    int k0 = kt * 16 + (lane & 3) * 2;
    float2 h01 = *(const float2*)&h0[(size_t)b * H_SZ + k0];
    float2 h89 = *(const float2*)&h0[(size_t)b * H_SZ + k0 + 8];
    uint4 v;
    v.x = pk_bf16(h01.x, h01.y, 0);
    v.y = pk_bf16(h89.x, h89.y, 0);
    v.z = pk_bf16(h01.x, h01.y, 1);
    v.w = pk_bf16(h89.x, h89.y, 1);
    g_h[(((size_t)nt * KT_N) + kt) * 32 + lane] = v;
}

// ---------------- main persistent kernel ----------------
__global__ void __launch_bounds__(NTH, 1)
gru_main(const float* __restrict__ inp,     // [T,B,3]
         const float* __restrict__ h0,      // [B,H]
         const float* __restrict__ wih,     // [3H,3]
         const float* __restrict__ bias,    // [3H]
         const float* __restrict__ bias_n,  // [H]
         float* __restrict__ out)           // [T,B]
{
    extern __shared__ float smf[];

    const int tid  = threadIdx.x;
    const int wid  = tid >> 5;          // 0..7 = k-split slice
    const int lane = tid & 31;
    const int m    = blockIdx.x;
    const int kt0  = wid * KT_PW;

    unsigned rel_base = 0;
    if (tid == 0) rel_base = atomicAdd(&g_release, 0u);

    // ---- one-time CTA-resident state: h_old, gate coefs, bias_n -> persistent smem ----
    for (int idx = tid; idx < 16 * 64; idx += NTH) {
        int kk = idx >> 6, b = idx & 63;
        smf[SM_HF + idx] = h0[(size_t)b * H_SZ + m * 16 + kk];
    }
    for (int idx = tid; idx < 192; idx += NTH) {
        int u  = m * 16 + idx / 12;
        int g  = (idx % 12) >> 2;
        int cf = idx & 3;
        int grow = g * H_SZ + u;
        smf[SM_GC + idx] = (cf < 3) ? wih[grow * 3 + cf] : bias[grow];
    }
    if (tid < 16) smf[SM_BN + tid] = bias_n[m * 16 + tid];
    __syncthreads();

    // A pointers for the 3 gate tiles (mt = m + 128*g)
    const uint4* pW[3];
    const uint4* pWl[3];
    #pragma unroll
    for (int g = 0; g < 3; g++) {
        pW[g]  = g_w + (((size_t)(m + 128 * g)) * KT_N + kt0) * 32 + lane;
        pWl[g] = pW[g] + (size_t)MT_TOT * KT_N * 32;
    }

    for (int t = 0; t < T_STEPS; t++) {
        // prefetch this step's input projection operands (consumed after GEMM)
        const float* xt = inp + (size_t)t * (B_SZ * 3) + (tid & 63) * 3;
        float x0 = __ldg(xt), x1 = __ldg(xt + 1), x2 = __ldg(xt + 2);

        float acc[3][8][4];
        #pragma unroll
        for (int g = 0; g < 3; g++)
            #pragma unroll
            for (int nt = 0; nt < 8; nt++)
                #pragma unroll
                for (int j = 0; j < 4; j++) acc[g][nt][j] = 0.0f;

        // B loads are plain LDG (L1-cached); safe: barrier's gpu-scope fence
        // IVALLs L1 every step. Each B/A line read exactly once per CTA.
        const uint4* pH = g_h + (size_t)(t & 1) * HBUF + (size_t)kt0 * 32 + lane;

        uint4 Ah[3], Al[3], Bv[8];
        #pragma unroll
        for (int g = 0; g < 3; g++) { Ah[g] = pW[g][0]; Al[g] = pWl[g][0]; }
        #pragma unroll
        for (int nt = 0; nt < 8; nt++) Bv[nt] = pH[(size_t)nt * KT_N * 32];

        #pragma unroll 2
        for (int kt = 0; kt < KT_PW; kt++) {
            uint4 nAh[3], nAl[3], nBv[8];
            #pragma unroll
            for (int g = 0; g < 3; g++) {            // padded: unconditional prefetch
                nAh[g] = pW[g][(kt + 1) * 32];
                nAl[g] = pWl[g][(kt + 1) * 32];
            }
            #pragma unroll
            for (int nt = 0; nt < 8; nt++)
                nBv[nt] = pH[(kt + 1) * 32 + (size_t)nt * KT_N * 32];

            #pragma unroll
            for (int g = 0; g < 3; g++)
                #pragma unroll
                for (int nt = 0; nt < 8; nt++) {
                    MMAOP(acc[g][nt], Ah[g], Bv[nt].x, Bv[nt].y);   // Whi*hhi
                    MMAOP(acc[g][nt], Ah[g], Bv[nt].z, Bv[nt].w);   // Whi*hlo
                    MMAOP(acc[g][nt], Al[g], Bv[nt].x, Bv[nt].y);   // Wlo*hhi
                }
            #pragma unroll
            for (int g = 0; g < 3; g++) { Ah[g] = nAh[g]; Al[g] = nAl[g]; }
            #pragma unroll
            for (int nt = 0; nt < 8; nt++) Bv[nt] = nBv[nt];
        }

        // ------------- partials -> smem -------------
        {
            int r0 = lane >> 2, c0 = (lane & 3) * 2;
            #pragma unroll
            for (int g = 0; g < 3; g++) {
                int rbase = (wid * 3 + g) * 16;
                #pragma unroll
                for (int nt = 0; nt < 8; nt++) {
                    *(float2*)&smf[SM_DP + (rbase + r0) * COLP + nt * 8 + c0]     = make_float2(acc[g][nt][0], acc[g][nt][1]);
                    *(float2*)&smf[SM_DP + (rbase + r0 + 8) * COLP + nt * 8 + c0] = make_float2(acc[g][nt][2], acc[g][nt][3]);
                }
            }
        }
        __syncthreads();

        // ------------- gate phase (all 256 threads; operands SMEM-resident) -------------
        {
            const int b  = tid & 63;
            const int kg = tid >> 6;               // 0..3
            float hn[4];
            #pragma unroll
            for (int i = 0; i < 4; i++) {
                int kk = kg * 2 + (i & 1) + (i >> 1) * 8;   // {2kg, 2kg+1, 2kg+8, 2kg+9}
                float dsum[3];
                #pragma unroll
                for (int g = 0; g < 3; g++) {
                    float s = 0.0f;
                    #pragma unroll
                    for (int p = 0; p < KS_N; p++)
                        s += smf[SM_DP + ((p * 3 + g) * 16 + kk) * COLP + b];
                    dsum[g] = s;
                }
                const float* gc = &smf[SM_GC + kk * 12];
                float igr = gc[3]  + x0 * gc[0] + x1 * gc[1] + x2 * gc[2];
                float igz = gc[7]  + x0 * gc[4] + x1 * gc[5] + x2 * gc[6];
                float ign = gc[11] + x0 * gc[8] + x1 * gc[9] + x2 * gc[10];
                float hold = smf[SM_HF + kk * 64 + b];
                float rg = 1.0f / (1.0f + expf(-(igr + dsum[0])));
                float zg = 1.0f / (1.0f + expf(-(igz + dsum[1])));
                float nn = tanhf(ign + rg * (dsum[2] + smf[SM_BN + kk]));
                float h2 = nn + zg * (hold - nn);
                hn[i] = h2;
                smf[SM_HF + kk * 64 + b] = h2;
            }
            // publish h fragment uint4 (hi+lo) into parity (t+1) buffer; kt column = m
            int nt    = b >> 3;
            int lane2 = (b & 7) * 4 + kg;
            uint4 v;
            v.x = pk_bf16(hn[0], hn[1], 0);
            v.y = pk_bf16(hn[2], hn[3], 0);
            v.z = pk_bf16(hn[0], hn[1], 1);
            v.w = pk_bf16(hn[2], hn[3], 1);
            g_h[(size_t)((t + 1) & 1) * HBUF + (((size_t)nt * KT_N) + m) * 32 + lane2] = v;
            if (m == 0 && kg == 0) out[(size_t)t * B_SZ + b] = hn[0];  // u == 0
        }

        // ------------- two-level grid barrier (low-contention arrival) -------------
        __syncthreads();
        if (tid == 0) {
            __threadfence();                        // publish h stores (release)
            unsigned* leaf = &g_leaf[(m >> 3) * 32];
            unsigned lp = atomicAdd(leaf, 1u);
            if (lp == 7u) {                         // last of this 8-CTA group
                atomicExch(leaf, 0u);
                unsigned rp2 = atomicAdd(&g_root, 1u);
                if (rp2 == 15u) {                   // last group
                    atomicExch(&g_root, 0u);
                    __threadfence();
                    atomicAdd(&g_release, 1u);
                }
            }
            unsigned tgt = rel_base + (unsigned)t + 1u;
            volatile unsigned* rl = &g_release;     // plain L2 poll, no atomic serialization
            while (*rl < tgt) { }
            __threadfence();                        // acquire + CCTL.IVALL (L1 invalidate)
        }
        __syncthreads();
    }
}

extern "C" void kernel_launch(void* const* d_in, const int* in_sizes, int n_in,
                              void* d_out, int out_size) {
    const float* inp  = (const float*)d_in[0];  // [T,B,3]
    const float* h0   = (const float*)d_in[1];  // [B,H]
    const float* wih  = (const float*)d_in[2];  // [3H,3]
    const float* whh  = (const float*)d_in[3];  // [3H,H]
    const float* bias = (const float*)d_in[4];  // [3H]
    const float* bn   = (const float*)d_in[5];  // [H]
    float* out = (float*)d_out;                 // [T,B]

    cudaFuncSetAttribute(gru_main, cudaFuncAttributeMaxDynamicSharedMemorySize, SMEM_DYN);

    w_init<<<12288, 256>>>(whh);   // 3,145,728 tasks
    h_init<<<128, 256>>>(h0);      // 32,768 tasks
    gru_main<<<NCTA, NTH, SMEM_DYN>>>(inp, h0, wih, bias, bn, out);
}